// round 12
// baseline (speedup 1.0000x reference)
#include <cuda_runtime.h>
#include <cuda_fp16.h>
#include <stdint.h>

#define Bb 256
#define Tt 512
#define Dd 128
#define Hh 512
#define Cc 10

#define NCTA 128        // 16 batch tiles x 8 h tiles
#define NTH  256
#define GRP  8          // CTAs per batch-tile barrier group
#define BM   16         // batch rows per CTA
#define HC   64         // h outputs per CTA

// ---- shared memory layout (bytes) ----
#define LDW 520                 // padded row stride in halves (512+8)
#define OFF_A   0               // c tile: 16 x 520 halves = 16640 B
#define OFF_W   16640           // weight stage: 64 x 520 halves = 66560 B (Wo parked here)
#define OFF_TOK 83200           // uchar [512][16] staged tokens (8192 B)
#define OFF_CM  91392           // float [16][65] master c (4160 B)
#define LDCM 65
#define OFF_LUT 95552           // float [4][3][64] (3072 B)
#define SMEM_TOTAL 98624

// ---- device globals (no allocation allowed) ----
__device__ __half g_ch[2][Bb*Hh];        // double-buffered fp16 c exchange
__device__ __half g_Wh[3][Hh*Hh];        // fp16 Wfh, Wih, Woh
__device__ float  g_h[Bb*Hh];            // final hidden state
__device__ float  g_lut[4*3*Hh];         // gate LUT; gate 3 (cs) pre-sigmoided
__device__ unsigned char g_xT[Tt*Bb];    // tokens transposed to [T][B]
__device__ volatile int g_flags[NCTA];   // per-CTA monotonic step flags

// =============== setup kernel ===============
__global__ void setup_kernel(const int* __restrict__ x, const float* __restrict__ emb,
    const float* __restrict__ Wfx, const float* __restrict__ bf,
    const float* __restrict__ Wix, const float* __restrict__ bi,
    const float* __restrict__ Wox, const float* __restrict__ bo,
    const float* __restrict__ Wcx, const float* __restrict__ bc,
    const float* __restrict__ Wfh, const float* __restrict__ Wih,
    const float* __restrict__ Woh)
{
    int id = blockIdx.x*blockDim.x + threadIdx.x;
    int n  = gridDim.x*blockDim.x;
    // gate LUT: [gate][val][h]
    for (int i = id; i < 4*3*Hh; i += n){
        int g = i/(3*Hh); int rem = i%(3*Hh); int v = rem/Hh; int h = rem%Hh;
        const float *W, *bb_;
        if      (g==0){ W=Wfx; bb_=bf; }
        else if (g==1){ W=Wix; bb_=bi; }
        else if (g==2){ W=Wox; bb_=bo; }
        else          { W=Wcx; bb_=bc; }
        float s = bb_[h];
        const float* e = emb + v*Dd;
        const float* w = W + (size_t)h*Dd;
        #pragma unroll 4
        for (int d = 0; d < Dd; d++) s += e[d]*w[d];
        if (g==3) s = 1.f/(1.f+expf(-s));   // pre-apply sigmoid to c~ gate
        g_lut[i] = s;
    }
    // zero both c exchange buffers (c0 = 0)
    for (int i = id; i < Bb*Hh; i += n){
        g_ch[0][i] = __float2half(0.f);
        g_ch[1][i] = __float2half(0.f);
    }
    // fp16 recurrent weights
    for (int i = id; i < Hh*Hh; i += n){
        g_Wh[0][i] = __float2half(Wfh[i]);
        g_Wh[1][i] = __float2half(Wih[i]);
        g_Wh[2][i] = __float2half(Woh[i]);
    }
    // transpose tokens
    for (int i = id; i < Tt*Bb; i += n){
        int tt = i / Bb, bb2 = i % Bb;
        g_xT[i] = (unsigned char)x[bb2*Tt + tt];
    }
    for (int i = id; i < NCTA; i += n) g_flags[i] = 0;
}

// =============== PTX helpers ===============
__device__ __forceinline__ void cpa16(uint32_t s, const void* g){
    asm volatile("cp.async.cg.shared.global [%0], [%1], 16;\n" :: "r"(s), "l"(g));
}
__device__ __forceinline__ void cpa_commit_wait(){
    asm volatile("cp.async.commit_group;\n");
    asm volatile("cp.async.wait_group 0;\n");
}
__device__ __forceinline__ void ldsm_x4(uint32_t &r0,uint32_t &r1,uint32_t &r2,uint32_t &r3, uint32_t a){
    asm volatile("ldmatrix.sync.aligned.m8n8.x4.shared.b16 {%0,%1,%2,%3}, [%4];\n"
        : "=r"(r0),"=r"(r1),"=r"(r2),"=r"(r3) : "r"(a));
}
__device__ __forceinline__ void ldsm_x2(uint32_t &r0,uint32_t &r1, uint32_t a){
    asm volatile("ldmatrix.sync.aligned.m8n8.x2.shared.b16 {%0,%1}, [%2];\n"
        : "=r"(r0),"=r"(r1) : "r"(a));
}
__device__ __forceinline__ void mma16816(float* c,
    uint32_t a0,uint32_t a1,uint32_t a2,uint32_t a3, uint32_t b0,uint32_t b1){
    asm volatile("mma.sync.aligned.m16n8k16.row.col.f32.f16.f16.f32 "
        "{%0,%1,%2,%3},{%4,%5,%6,%7},{%8,%9},{%0,%1,%2,%3};\n"
        : "+f"(c[0]),"+f"(c[1]),"+f"(c[2]),"+f"(c[3])
        : "r"(a0),"r"(a1),"r"(a2),"r"(a3),"r"(b0),"r"(b1));
}
__device__ __forceinline__ float sigm(float x){ return 1.f/(1.f+__expf(-x)); }

// =============== persistent LSTM kernel ===============
__global__ void __launch_bounds__(NTH, 1) lstm_kernel()
{
    extern __shared__ char smem[];
    uint32_t sbase = (uint32_t)__cvta_generic_to_shared(smem);
    int tid = threadIdx.x;
    int cta = blockIdx.x;
    int jt = cta & 7;            // h tile (0-7)
    int mt = cta >> 3;           // batch tile / barrier group (0-15)
    int b0 = mt*BM, h0 = jt*HC;

    float* sCm = (float*)(smem + OFF_CM);
    float* sLut = (float*)(smem + OFF_LUT);
    unsigned char* sTok = (unsigned char*)(smem + OFF_TOK);

    int wid = tid >> 5, lane = tid & 31;
    int g4 = lane >> 2, t4 = lane & 3;

    // --- per-warp mma geometry ---
    // A fragment (16x16 per k-step), m0 = 0
    uint32_t aA0 = sbase + OFF_A +
        (uint32_t)(((lane & 15)*LDW) + ((lane >> 4) & 1)*8)*2;
    // B fragment: warp wid owns n8 rows wid*8..wid*8+7 of the 64-row weight slice
    int rowBn = wid*8 + (lane & 7);
    uint32_t colBn = ((lane >> 3) & 1) * 8;
    uint32_t aBW = sbase + OFF_W + (uint32_t)(rowBn*LDW + colBn)*2;

    // --- stage + hoist weights (once) ---
    uint32_t Bf[64], Bi[64];
    for (int i = tid; i < 64*64; i += NTH){
        int r = i >> 6, ck = i & 63;
        cpa16(sbase + OFF_W + (uint32_t)(r*LDW + ck*8)*2,
              &g_Wh[0][(size_t)(h0+r)*Hh + ck*8]);
    }
    cpa_commit_wait();
    __syncthreads();
    #pragma unroll
    for (int ks = 0; ks < 32; ks++)
        ldsm_x2(Bf[2*ks], Bf[2*ks+1], aBW + ks*32);
    __syncthreads();
    for (int i = tid; i < 64*64; i += NTH){
        int r = i >> 6, ck = i & 63;
        cpa16(sbase + OFF_W + (uint32_t)(r*LDW + ck*8)*2,
              &g_Wh[1][(size_t)(h0+r)*Hh + ck*8]);
    }
    cpa_commit_wait();
    __syncthreads();
    #pragma unroll
    for (int ks = 0; ks < 32; ks++)
        ldsm_x2(Bi[2*ks], Bi[2*ks+1], aBW + ks*32);
    __syncthreads();
    // Wo -> SMEM (parked there until t = Tt-1)
    for (int i = tid; i < 64*64; i += NTH){
        int r = i >> 6, ck = i & 63;
        cpa16(sbase + OFF_W + (uint32_t)(r*LDW + ck*8)*2,
              &g_Wh[2][(size_t)(h0+r)*Hh + ck*8]);
    }
    // LUT slice + master c init + token staging
    for (int i = tid; i < 4*3*HC; i += NTH){
        int g = i/(3*HC), v = (i/HC)%3, h = i%HC;
        sLut[(g*3+v)*HC + h] = g_lut[(g*3+v)*Hh + h0 + h];
    }
    for (int i = tid; i < BM*LDCM; i += NTH) sCm[i] = 0.f;
    for (int i = tid; i < Tt*BM; i += NTH){
        int tt = i >> 4, bb2 = i & 15;
        sTok[i] = g_xT[tt*Bb + b0 + bb2];
    }
    cpa_commit_wait();
    __syncthreads();

    // elementwise cell ownership (matches mma accumulator layout)
    int r1 = g4, r2 = g4 + 8;
    int c0 = wid*8 + t4*2;

    volatile int* fl = g_flags + (mt << 3);
    int myProdCol = wid*64;      // warp wid owns producer wid's 64-column slice

    for (int t = 0; t < Tt; t++){
        int buf = t & 1;

        // --- per-warp fused poll + slice load ---
        // warp wid waits ONLY for producer wid, then immediately loads its slice
        while (fl[wid] < t) { }
        const __half* csrc = g_ch[buf] + (size_t)b0*Hh;
        #pragma unroll
        for (int u = 0; u < 4; u++){
            int idx = u*32 + lane;       // 0..127
            int r = idx >> 3;            // 0..15
            int q = idx & 7;             // 16B chunk within 64 cols
            int col = myProdCol + q*8;
            cpa16(sbase + OFF_A + (uint32_t)(r*LDW + col)*2,
                  csrc + r*Hh + col);
        }
        cpa_commit_wait();
        __syncthreads();                 // all 8 slices visible to all warps

        // --- GEMM: f and i for the SAME (b,h) positions per warp; B in registers ---
        float accF[4] = {0,0,0,0}, accI[4] = {0,0,0,0};
        #pragma unroll
        for (int ks = 0; ks < 32; ks++){
            uint32_t a0,a1,a2,a3;
            ldsm_x4(a0,a1,a2,a3, aA0 + ks*32);
            mma16816(accF, a0,a1,a2,a3, Bf[2*ks], Bf[2*ks+1]);
            mma16816(accI, a0,a1,a2,a3, Bi[2*ks], Bi[2*ks+1]);
        }

        // --- elementwise entirely in registers (static per-lane cell ownership) ---
        int v1 = (int)sTok[(t << 4) + r1];
        int v2 = (int)sTok[(t << 4) + r2];
        const float* lutF1 = sLut + (0*3+v1)*HC;
        const float* lutI1 = sLut + (1*3+v1)*HC;
        const float* lutC1 = sLut + (3*3+v1)*HC;
        const float* lutF2 = sLut + (0*3+v2)*HC;
        const float* lutI2 = sLut + (1*3+v2)*HC;
        const float* lutC2 = sLut + (3*3+v2)*HC;

        float f00 = sigm(accF[0] + lutF1[c0]);
        float f01 = sigm(accF[1] + lutF1[c0+1]);
        float f10 = sigm(accF[2] + lutF2[c0]);
        float f11 = sigm(accF[3] + lutF2[c0+1]);
        float i00 = sigm(accI[0] + lutI1[c0]);
        float i01 = sigm(accI[1] + lutI1[c0+1]);
        float i10 = sigm(accI[2] + lutI2[c0]);
        float i11 = sigm(accI[3] + lutI2[c0+1]);

        float cn00 = lutC1[c0]  *i00 + sCm[r1*LDCM + c0]  *f00;
        float cn01 = lutC1[c0+1]*i01 + sCm[r1*LDCM + c0+1]*f01;
        float cn10 = lutC2[c0]  *i10 + sCm[r2*LDCM + c0]  *f10;
        float cn11 = lutC2[c0+1]*i11 + sCm[r2*LDCM + c0+1]*f11;
        sCm[r1*LDCM + c0]   = cn00;
        sCm[r1*LDCM + c0+1] = cn01;
        sCm[r2*LDCM + c0]   = cn10;
        sCm[r2*LDCM + c0+1] = cn11;

        if (t < Tt-1){
            *(__half2*)&g_ch[buf^1][(size_t)(b0+r1)*Hh + h0 + c0] =
                __halves2half2(__float2half(cn00), __float2half(cn01));
            *(__half2*)&g_ch[buf^1][(size_t)(b0+r2)*Hh + h0 + c0] =
                __halves2half2(__float2half(cn10), __float2half(cn11));
            // all A-tile reads + c stores complete before flag release
            __syncthreads();
            if (tid == 0){
                __threadfence();
                g_flags[cta] = t+1;
            }
        } else {
            // o-gate matvec (once), Wo parked in SMEM staging buffer
            float acco[4] = {0,0,0,0};
            #pragma unroll 8
            for (int ks = 0; ks < 32; ks++){
                uint32_t a0,a1,a2,a3,o0,o1;
                ldsm_x4(a0,a1,a2,a3, aA0 + ks*32);
                ldsm_x2(o0,o1, aBW + ks*32);
                mma16816(acco, a0,a1,a2,a3, o0,o1);
            }
            const float* lutO1 = sLut + (2*3+v1)*HC;
            const float* lutO2 = sLut + (2*3+v2)*HC;
            g_h[(size_t)(b0+r1)*Hh + h0 + c0]   = tanhf(cn00)*sigm(acco[0] + lutO1[c0]);
            g_h[(size_t)(b0+r1)*Hh + h0 + c0+1] = tanhf(cn01)*sigm(acco[1] + lutO1[c0+1]);
            g_h[(size_t)(b0+r2)*Hh + h0 + c0]   = tanhf(cn10)*sigm(acco[2] + lutO2[c0]);
            g_h[(size_t)(b0+r2)*Hh + h0 + c0+1] = tanhf(cn11)*sigm(acco[3] + lutO2[c0+1]);
        }
    }
}

// =============== classifier + log_softmax ===============
__global__ void cls_kernel(const float* __restrict__ Wph, const float* __restrict__ bp,
                           float* __restrict__ out)
{
    int b = blockIdx.x, lane = threadIdx.x;
    const float* hr = g_h + (size_t)b*Hh;
    float p[Cc];
    #pragma unroll
    for (int c = 0; c < Cc; c++){
        float s = 0.f;
        for (int k = lane; k < Hh; k += 32) s += hr[k]*Wph[c*Hh + k];
        #pragma unroll
        for (int o = 16; o; o >>= 1) s += __shfl_xor_sync(0xffffffffu, s, o);
        p[c] = s + bp[c];
    }
    float mx = p[0];
    #pragma unroll
    for (int c = 1; c < Cc; c++) mx = fmaxf(mx, p[c]);
    float se = 0.f;
    #pragma unroll
    for (int c = 0; c < Cc; c++) se += expf(p[c]-mx);
    float lse = mx + logf(se);
    if (lane < Cc) out[b*Cc + lane] = p[lane] - lse;
}

// =============== launch ===============
extern "C" void kernel_launch(void* const* d_in, const int* in_sizes, int n_in,
                              void* d_out, int out_size)
{
    const int*   x   = (const int*)  d_in[0];
    const float* emb = (const float*)d_in[1];
    const float* Wfx = (const float*)d_in[2];
    const float* Wfh = (const float*)d_in[3];
    const float* bf  = (const float*)d_in[4];
    const float* Wix = (const float*)d_in[5];
    const float* Wih = (const float*)d_in[6];
    const float* bi  = (const float*)d_in[7];
    const float* Wox = (const float*)d_in[8];
    const float* Woh = (const float*)d_in[9];
    const float* bo  = (const float*)d_in[10];
    const float* Wcx = (const float*)d_in[11];
    const float* bc  = (const float*)d_in[12];
    const float* Wph = (const float*)d_in[13];
    const float* bp  = (const float*)d_in[14];
    float* out = (float*)d_out;

    cudaFuncSetAttribute(lstm_kernel,
        cudaFuncAttributeMaxDynamicSharedMemorySize, SMEM_TOTAL);

    setup_kernel<<<256,256>>>(x, emb, Wfx, bf, Wix, bi, Wox, bo, Wcx, bc,
                              Wfh, Wih, Woh);
    lstm_kernel<<<NCTA, NTH, SMEM_TOTAL>>>();
    cls_kernel<<<Bb, 32>>>(Wph, bp, out);
}

// round 13
// speedup vs baseline: 1.9756x; 1.9756x over previous
#include <cuda_runtime.h>
#include <cuda_fp16.h>
#include <stdint.h>

#define Bb 256
#define Tt 512
#define Dd 128
#define Hh 512
#define Cc 10

#define NCTA 128        // 16 batch tiles x 8 h tiles
#define NTH  256
#define GRP  8          // CTAs per batch-tile barrier group
#define BM   16         // batch rows per CTA
#define HC   64         // h outputs per CTA

// ---- shared memory layout (bytes) ----
#define LDW 520                 // padded row stride in halves (512+8)
#define OFF_A   0               // c tile: 16 x 520 halves = 16640 B
#define OFF_W   16640           // weight stage: 64 x 520 halves = 66560 B (Wo parked here)
#define OFF_TOK 83200           // uchar [512][16] staged tokens (8192 B)
#define OFF_CM  91392           // float [16][65] master c (4160 B)
#define LDCM 65
#define OFF_LUT 95552           // float [4][3][64] (3072 B)
#define SMEM_TOTAL 98624

// ---- device globals (no allocation allowed) ----
__device__ __half g_ch[2][Bb*Hh];        // double-buffered fp16 c exchange
__device__ __half g_Wh[3][Hh*Hh];        // fp16 Wfh, Wih, Woh
__device__ float  g_h[Bb*Hh];            // final hidden state
__device__ float  g_lut[4*3*Hh];         // gate LUT; gate 3 (cs) pre-sigmoided
__device__ unsigned char g_xT[Tt*Bb];    // tokens transposed to [T][B]
__device__ volatile int g_flags[NCTA];   // per-CTA monotonic step flags

// =============== setup kernel ===============
__global__ void setup_kernel(const int* __restrict__ x, const float* __restrict__ emb,
    const float* __restrict__ Wfx, const float* __restrict__ bf,
    const float* __restrict__ Wix, const float* __restrict__ bi,
    const float* __restrict__ Wox, const float* __restrict__ bo,
    const float* __restrict__ Wcx, const float* __restrict__ bc,
    const float* __restrict__ Wfh, const float* __restrict__ Wih,
    const float* __restrict__ Woh)
{
    int id = blockIdx.x*blockDim.x + threadIdx.x;
    int n  = gridDim.x*blockDim.x;
    // gate LUT: [gate][val][h]
    for (int i = id; i < 4*3*Hh; i += n){
        int g = i/(3*Hh); int rem = i%(3*Hh); int v = rem/Hh; int h = rem%Hh;
        const float *W, *bb_;
        if      (g==0){ W=Wfx; bb_=bf; }
        else if (g==1){ W=Wix; bb_=bi; }
        else if (g==2){ W=Wox; bb_=bo; }
        else          { W=Wcx; bb_=bc; }
        float s = bb_[h];
        const float* e = emb + v*Dd;
        const float* w = W + (size_t)h*Dd;
        #pragma unroll 4
        for (int d = 0; d < Dd; d++) s += e[d]*w[d];
        if (g==3) s = 1.f/(1.f+expf(-s));   // pre-apply sigmoid to c~ gate
        g_lut[i] = s;
    }
    // zero both c exchange buffers (c0 = 0)
    for (int i = id; i < Bb*Hh; i += n){
        g_ch[0][i] = __float2half(0.f);
        g_ch[1][i] = __float2half(0.f);
    }
    // fp16 recurrent weights
    for (int i = id; i < Hh*Hh; i += n){
        g_Wh[0][i] = __float2half(Wfh[i]);
        g_Wh[1][i] = __float2half(Wih[i]);
        g_Wh[2][i] = __float2half(Woh[i]);
    }
    // transpose tokens
    for (int i = id; i < Tt*Bb; i += n){
        int tt = i / Bb, bb2 = i % Bb;
        g_xT[i] = (unsigned char)x[bb2*Tt + tt];
    }
    for (int i = id; i < NCTA; i += n) g_flags[i] = 0;
}

// =============== PTX helpers ===============
__device__ __forceinline__ void cpa16(uint32_t s, const void* g){
    asm volatile("cp.async.cg.shared.global [%0], [%1], 16;\n" :: "r"(s), "l"(g));
}
__device__ __forceinline__ void cpa_commit_wait(){
    asm volatile("cp.async.commit_group;\n");
    asm volatile("cp.async.wait_group 0;\n");
}
__device__ __forceinline__ void ldsm_x4(uint32_t &r0,uint32_t &r1,uint32_t &r2,uint32_t &r3, uint32_t a){
    asm volatile("ldmatrix.sync.aligned.m8n8.x4.shared.b16 {%0,%1,%2,%3}, [%4];\n"
        : "=r"(r0),"=r"(r1),"=r"(r2),"=r"(r3) : "r"(a));
}
__device__ __forceinline__ void ldsm_x2(uint32_t &r0,uint32_t &r1, uint32_t a){
    asm volatile("ldmatrix.sync.aligned.m8n8.x2.shared.b16 {%0,%1}, [%2];\n"
        : "=r"(r0),"=r"(r1) : "r"(a));
}
__device__ __forceinline__ void mma16816(float* c,
    uint32_t a0,uint32_t a1,uint32_t a2,uint32_t a3, uint32_t b0,uint32_t b1){
    asm volatile("mma.sync.aligned.m16n8k16.row.col.f32.f16.f16.f32 "
        "{%0,%1,%2,%3},{%4,%5,%6,%7},{%8,%9},{%0,%1,%2,%3};\n"
        : "+f"(c[0]),"+f"(c[1]),"+f"(c[2]),"+f"(c[3])
        : "r"(a0),"r"(a1),"r"(a2),"r"(a3),"r"(b0),"r"(b1));
}
__device__ __forceinline__ float sigm(float x){ return 1.f/(1.f+__expf(-x)); }

// =============== persistent LSTM kernel ===============
__global__ void __launch_bounds__(NTH, 1) lstm_kernel()
{
    extern __shared__ char smem[];
    uint32_t sbase = (uint32_t)__cvta_generic_to_shared(smem);
    int tid = threadIdx.x;
    int cta = blockIdx.x;
    int jt = cta & 7;            // h tile (0-7)
    int mt = cta >> 3;           // batch tile / barrier group (0-15)
    int b0 = mt*BM, h0 = jt*HC;

    float* sCm = (float*)(smem + OFF_CM);
    float* sLut = (float*)(smem + OFF_LUT);
    unsigned char* sTok = (unsigned char*)(smem + OFF_TOK);

    int wid = tid >> 5, lane = tid & 31;
    int g4 = lane >> 2, t4 = lane & 3;

    // --- per-warp mma geometry ---
    uint32_t aA0 = sbase + OFF_A +
        (uint32_t)(((lane & 15)*LDW) + ((lane >> 4) & 1)*8)*2;
    int rowBn = wid*8 + (lane & 7);
    uint32_t colBn = ((lane >> 3) & 1) * 8;
    uint32_t aBW = sbase + OFF_W + (uint32_t)(rowBn*LDW + colBn)*2;

    // --- stage + hoist weights (once) ---
    uint32_t Bf[64], Bi[64];
    for (int i = tid; i < 64*64; i += NTH){
        int r = i >> 6, ck = i & 63;
        cpa16(sbase + OFF_W + (uint32_t)(r*LDW + ck*8)*2,
              &g_Wh[0][(size_t)(h0+r)*Hh + ck*8]);
    }
    cpa_commit_wait();
    __syncthreads();
    #pragma unroll
    for (int ks = 0; ks < 32; ks++)
        ldsm_x2(Bf[2*ks], Bf[2*ks+1], aBW + ks*32);
    __syncthreads();
    for (int i = tid; i < 64*64; i += NTH){
        int r = i >> 6, ck = i & 63;
        cpa16(sbase + OFF_W + (uint32_t)(r*LDW + ck*8)*2,
              &g_Wh[1][(size_t)(h0+r)*Hh + ck*8]);
    }
    cpa_commit_wait();
    __syncthreads();
    #pragma unroll
    for (int ks = 0; ks < 32; ks++)
        ldsm_x2(Bi[2*ks], Bi[2*ks+1], aBW + ks*32);
    __syncthreads();
    // Wo -> SMEM (parked there until t = Tt-1)
    for (int i = tid; i < 64*64; i += NTH){
        int r = i >> 6, ck = i & 63;
        cpa16(sbase + OFF_W + (uint32_t)(r*LDW + ck*8)*2,
              &g_Wh[2][(size_t)(h0+r)*Hh + ck*8]);
    }
    // LUT slice + master c init + token staging
    for (int i = tid; i < 4*3*HC; i += NTH){
        int g = i/(3*HC), v = (i/HC)%3, h = i%HC;
        sLut[(g*3+v)*HC + h] = g_lut[(g*3+v)*Hh + h0 + h];
    }
    for (int i = tid; i < BM*LDCM; i += NTH) sCm[i] = 0.f;
    for (int i = tid; i < Tt*BM; i += NTH){
        int tt = i >> 4, bb2 = i & 15;
        sTok[i] = g_xT[tt*Bb + b0 + bb2];
    }
    cpa_commit_wait();
    __syncthreads();

    // elementwise cell ownership (matches mma accumulator layout)
    int r1 = g4, r2 = g4 + 8;
    int c0 = wid*8 + t4*2;

    volatile int* fl = g_flags + (mt << 3);

    for (int t = 0; t < Tt; t++){
        int buf = t & 1;

        // --- group barrier (proven R9 mechanism): 8 threads poll, rest wait ---
        if (tid < GRP){
            while (fl[tid] < t) { }
        }
        __syncthreads();

        // --- c tile load: 2 committed column-halves (8 KB each) ---
        const __half* csrc = g_ch[buf] + (size_t)b0*Hh;
        #pragma unroll
        for (int u = 0; u < 2; u++){
            int i = u*NTH + tid;          // 0..511
            int r = i >> 5, ck = i & 31;  // cols 0..255
            cpa16(sbase + OFF_A + (uint32_t)(r*LDW + ck*8)*2,
                  csrc + r*Hh + ck*8);
        }
        asm volatile("cp.async.commit_group;\n");
        #pragma unroll
        for (int u = 0; u < 2; u++){
            int i = u*NTH + tid;          // 0..511
            int r = i >> 5, ck = 32 + (i & 31);  // cols 256..511
            cpa16(sbase + OFF_A + (uint32_t)(r*LDW + ck*8)*2,
                  csrc + r*Hh + ck*8);
        }
        asm volatile("cp.async.commit_group;\n");

        // --- GEMM first half on chunk 0 while chunk 1 is in flight ---
        float accF[4] = {0,0,0,0}, accI[4] = {0,0,0,0};
        asm volatile("cp.async.wait_group 1;\n");
        __syncthreads();
        #pragma unroll
        for (int ks = 0; ks < 16; ks++){
            uint32_t a0,a1,a2,a3;
            ldsm_x4(a0,a1,a2,a3, aA0 + ks*32);
            mma16816(accF, a0,a1,a2,a3, Bf[2*ks], Bf[2*ks+1]);
            mma16816(accI, a0,a1,a2,a3, Bi[2*ks], Bi[2*ks+1]);
        }
        asm volatile("cp.async.wait_group 0;\n");
        __syncthreads();
        #pragma unroll
        for (int ks = 16; ks < 32; ks++){
            uint32_t a0,a1,a2,a3;
            ldsm_x4(a0,a1,a2,a3, aA0 + ks*32);
            mma16816(accF, a0,a1,a2,a3, Bf[2*ks], Bf[2*ks+1]);
            mma16816(accI, a0,a1,a2,a3, Bi[2*ks], Bi[2*ks+1]);
        }

        // --- elementwise entirely in registers (static per-lane cell ownership) ---
        int v1 = (int)sTok[(t << 4) + r1];
        int v2 = (int)sTok[(t << 4) + r2];
        const float* lutF1 = sLut + (0*3+v1)*HC;
        const float* lutI1 = sLut + (1*3+v1)*HC;
        const float* lutC1 = sLut + (3*3+v1)*HC;
        const float* lutF2 = sLut + (0*3+v2)*HC;
        const float* lutI2 = sLut + (1*3+v2)*HC;
        const float* lutC2 = sLut + (3*3+v2)*HC;

        float f00 = sigm(accF[0] + lutF1[c0]);
        float f01 = sigm(accF[1] + lutF1[c0+1]);
        float f10 = sigm(accF[2] + lutF2[c0]);
        float f11 = sigm(accF[3] + lutF2[c0+1]);
        float i00 = sigm(accI[0] + lutI1[c0]);
        float i01 = sigm(accI[1] + lutI1[c0+1]);
        float i10 = sigm(accI[2] + lutI2[c0]);
        float i11 = sigm(accI[3] + lutI2[c0+1]);

        float cn00 = lutC1[c0]  *i00 + sCm[r1*LDCM + c0]  *f00;
        float cn01 = lutC1[c0+1]*i01 + sCm[r1*LDCM + c0+1]*f01;
        float cn10 = lutC2[c0]  *i10 + sCm[r2*LDCM + c0]  *f10;
        float cn11 = lutC2[c0+1]*i11 + sCm[r2*LDCM + c0+1]*f11;
        sCm[r1*LDCM + c0]   = cn00;
        sCm[r1*LDCM + c0+1] = cn01;
        sCm[r2*LDCM + c0]   = cn10;
        sCm[r2*LDCM + c0+1] = cn11;

        if (t < Tt-1){
            *(__half2*)&g_ch[buf^1][(size_t)(b0+r1)*Hh + h0 + c0] =
                __halves2half2(__float2half(cn00), __float2half(cn01));
            *(__half2*)&g_ch[buf^1][(size_t)(b0+r2)*Hh + h0 + c0] =
                __halves2half2(__float2half(cn10), __float2half(cn11));
            // all A-tile reads + c stores complete before flag release
            __syncthreads();
            if (tid == 0){
                __threadfence();
                g_flags[cta] = t+1;
            }
        } else {
            // o-gate matvec (once), Wo parked in SMEM staging buffer
            float acco[4] = {0,0,0,0};
            #pragma unroll 8
            for (int ks = 0; ks < 32; ks++){
                uint32_t a0,a1,a2,a3,o0,o1;
                ldsm_x4(a0,a1,a2,a3, aA0 + ks*32);
                ldsm_x2(o0,o1, aBW + ks*32);
                mma16816(acco, a0,a1,a2,a3, o0,o1);
            }
            const float* lutO1 = sLut + (2*3+v1)*HC;
            const float* lutO2 = sLut + (2*3+v2)*HC;
            g_h[(size_t)(b0+r1)*Hh + h0 + c0]   = tanhf(cn00)*sigm(acco[0] + lutO1[c0]);
            g_h[(size_t)(b0+r1)*Hh + h0 + c0+1] = tanhf(cn01)*sigm(acco[1] + lutO1[c0+1]);
            g_h[(size_t)(b0+r2)*Hh + h0 + c0]   = tanhf(cn10)*sigm(acco[2] + lutO2[c0]);
            g_h[(size_t)(b0+r2)*Hh + h0 + c0+1] = tanhf(cn11)*sigm(acco[3] + lutO2[c0+1]);
        }
    }
}

// =============== classifier + log_softmax ===============
__global__ void cls_kernel(const float* __restrict__ Wph, const float* __restrict__ bp,
                           float* __restrict__ out)
{
    int b = blockIdx.x, lane = threadIdx.x;
    const float* hr = g_h + (size_t)b*Hh;
    float p[Cc];
    #pragma unroll
    for (int c = 0; c < Cc; c++){
        float s = 0.f;
        for (int k = lane; k < Hh; k += 32) s += hr[k]*Wph[c*Hh + k];
        #pragma unroll
        for (int o = 16; o; o >>= 1) s += __shfl_xor_sync(0xffffffffu, s, o);
        p[c] = s + bp[c];
    }
    float mx = p[0];
    #pragma unroll
    for (int c = 1; c < Cc; c++) mx = fmaxf(mx, p[c]);
    float se = 0.f;
    #pragma unroll
    for (int c = 0; c < Cc; c++) se += expf(p[c]-mx);
    float lse = mx + logf(se);
    if (lane < Cc) out[b*Cc + lane] = p[lane] - lse;
}

// =============== launch ===============
extern "C" void kernel_launch(void* const* d_in, const int* in_sizes, int n_in,
                              void* d_out, int out_size)
{
    const int*   x   = (const int*)  d_in[0];
    const float* emb = (const float*)d_in[1];
    const float* Wfx = (const float*)d_in[2];
    const float* Wfh = (const float*)d_in[3];
    const float* bf  = (const float*)d_in[4];
    const float* Wix = (const float*)d_in[5];
    const float* Wih = (const float*)d_in[6];
    const float* bi  = (const float*)d_in[7];
    const float* Wox = (const float*)d_in[8];
    const float* Woh = (const float*)d_in[9];
    const float* bo  = (const float*)d_in[10];
    const float* Wcx = (const float*)d_in[11];
    const float* bc  = (const float*)d_in[12];
    const float* Wph = (const float*)d_in[13];
    const float* bp  = (const float*)d_in[14];
    float* out = (float*)d_out;

    cudaFuncSetAttribute(lstm_kernel,
        cudaFuncAttributeMaxDynamicSharedMemorySize, SMEM_TOTAL);

    setup_kernel<<<256,256>>>(x, emb, Wfx, bf, Wix, bi, Wox, bo, Wcx, bc,
                              Wfh, Wih, Woh);
    lstm_kernel<<<NCTA, NTH, SMEM_TOTAL>>>();
    cls_kernel<<<Bb, 32>>>(Wph, bp, out);
}